// round 4
// baseline (speedup 1.0000x reference)
#include <cuda_runtime.h>
#include <cuda_bf16.h>

#define BATCH 64
#define SEQT  80
#define EMBD  100
#define KPAD  128
#define UN    2048
#define NCTA  128
#define NTHR  512
#define CPB   16
#define CK    128
#define HST   132              // h smem row stride (floats)
#define WST   132              // w smem col stride (floats), 16B-aligned cols
#define HSZ   (BATCH*HST)      // 8448 floats
#define WSZ   (CPB*WST)        // 2112 floats
#define NBUF  3

typedef unsigned long long ull;

__device__ float g_h0[2][BATCH * UN];
__device__ float g_h1[2][BATCH * UN];
__device__ unsigned int g_bar;
// Pre-transposed weights: WT[n][k] = W[k][n]
__device__ float g_Wh0T[UN * UN];
__device__ float g_Wx1T[UN * UN];
__device__ float g_Wh1T[UN * UN];
__device__ float g_Wx0T[UN * KPAD];   // K padded 100 -> 128 with zeros

extern __shared__ float smem[];

#define FFMA2(acc, a, b) asm("fma.rn.f32x2 %0, %1, %2, %0;" : "+l"(acc) : "l"(a), "l"(b))

__device__ __forceinline__ void cp16(float* d, const float* s) {
    unsigned ds = (unsigned)__cvta_generic_to_shared(d);
    asm volatile("cp.async.ca.shared.global [%0], [%1], 16;" :: "r"(ds), "l"(s));
}
#define CP_COMMIT() asm volatile("cp.async.commit_group;" ::: "memory")
#define CP_WAIT1()  asm volatile("cp.async.wait_group 1;" ::: "memory")
#define CP_WAIT0()  asm volatile("cp.async.wait_group 0;" ::: "memory")

__global__ void rnn_init_kernel() {
    int idx = blockIdx.x * blockDim.x + threadIdx.x;
    for (int i = idx; i < BATCH * UN; i += gridDim.x * blockDim.x) {
        g_h0[1][i] = 0.0f;
        g_h1[1][i] = 0.0f;
    }
    if (idx == 0) g_bar = 0u;
}

// dst[n][kpad] = (k < K) ? src[k][n] : 0
__global__ void transpose_pad(const float* __restrict__ src, float* __restrict__ dst,
                              int K, int N, int Kpad) {
    __shared__ float tile[32][33];
    int kb = blockIdx.y * 32, nb = blockIdx.x * 32;
    int tx = threadIdx.x, ty = threadIdx.y;
    #pragma unroll
    for (int j = 0; j < 32; j += 8) {
        int k = kb + ty + j, n = nb + tx;
        tile[ty + j][tx] = (k < K && n < N) ? src[(size_t)k * N + n] : 0.0f;
    }
    __syncthreads();
    #pragma unroll
    for (int j = 0; j < 32; j += 8) {
        int n = nb + ty + j, k = kb + tx;
        if (n < N && k < Kpad) dst[(size_t)n * Kpad + k] = tile[tx][ty + j];
    }
}

__device__ __forceinline__ void gbar(unsigned int target) {
    __syncthreads();
    if (threadIdx.x == 0) {
        __threadfence();
        atomicAdd(&g_bar, 1u);
        unsigned int v;
        do {
            asm volatile("ld.acquire.gpu.u32 %0, [%1];" : "=r"(v) : "l"(&g_bar) : "memory");
        } while (v < target);
    }
    __syncthreads();
}

// Stage one K-chunk into buffer b.
// type 0: emb -> hs (pad 100..127), Wx0T slab -> wA
// type 1: h0prev -> hs, Wh0T -> wA (if dA), Wx1T -> wB (if dB)
// type 2: h1prev -> hs, Wh1T -> wB
__device__ __forceinline__ void stage_chunk(
    int type, int kc, int p, int b, bool dA, bool dB,
    const int* __restrict__ inputs, const float* __restrict__ emb,
    const float* __restrict__ h0prev, const float* __restrict__ h1prev,
    int cb, int tid)
{
    float* hs = smem + b * HSZ;
    float* wA = smem + NBUF * HSZ + b * (2 * WSZ);
    float* wB = wA + WSZ;
    if (type == 0) {
        for (int i = tid; i < BATCH * 25; i += NTHR) {
            int row = i / 25, c4 = i % 25;
            int tok = __ldg(&inputs[row * SEQT + p]);
            cp16(hs + row * HST + c4 * 4, emb + (size_t)tok * EMBD + c4 * 4);
        }
        float4 z = make_float4(0.f, 0.f, 0.f, 0.f);
        for (int i = tid; i < BATCH * 7; i += NTHR) {
            int row = i / 7, c4 = 25 + i % 7;
            *(float4*)(hs + row * HST + c4 * 4) = z;
        }
        for (int i = tid; i < CPB * 32; i += NTHR) {
            int c = i >> 5, q = i & 31;
            cp16(wA + c * WST + q * 4, g_Wx0T + (size_t)(cb + c) * KPAD + q * 4);
        }
    } else if (type == 1) {
        for (int i = tid; i < BATCH * 32; i += NTHR) {
            int row = i >> 5, c4 = i & 31;
            cp16(hs + row * HST + c4 * 4, h0prev + (size_t)row * UN + kc + c4 * 4);
        }
        if (dA)
            for (int i = tid; i < CPB * 32; i += NTHR) {
                int c = i >> 5, q = i & 31;
                cp16(wA + c * WST + q * 4, g_Wh0T + (size_t)(cb + c) * UN + kc + q * 4);
            }
        if (dB)
            for (int i = tid; i < CPB * 32; i += NTHR) {
                int c = i >> 5, q = i & 31;
                cp16(wB + c * WST + q * 4, g_Wx1T + (size_t)(cb + c) * UN + kc + q * 4);
            }
    } else {
        for (int i = tid; i < BATCH * 32; i += NTHR) {
            int row = i >> 5, c4 = i & 31;
            cp16(hs + row * HST + c4 * 4, h1prev + (size_t)row * UN + kc + c4 * 4);
        }
        for (int i = tid; i < CPB * 32; i += NTHR) {
            int c = i >> 5, q = i & 31;
            cp16(wB + c * WST + q * 4, g_Wh1T + (size_t)(cb + c) * UN + kc + q * 4);
        }
    }
}

// Compute 32-k slice: 4 rows (o+16j) x 2 cols (cg, cg+8) per tile.
template <bool CA, bool CB>
__device__ __forceinline__ void gemm32(int b, int kq, int o, int cg,
                                       ull accA[4][2], ull accB[4][2])
{
    const float* hs = smem + b * HSZ;
    const float* wA = smem + NBUF * HSZ + b * (2 * WSZ);
    const float* wB = wA + WSZ;
    const int kb = kq * 32;
    #pragma unroll
    for (int kk = 0; kk < 32; kk += 4) {
        const int k = kb + kk;
        ulonglong2 h[4];
        #pragma unroll
        for (int j = 0; j < 4; j++)
            h[j] = *(const ulonglong2*)(hs + (o + 16 * j) * HST + k);
        if (CA) {
            #pragma unroll
            for (int cc = 0; cc < 2; cc++) {
                ulonglong2 w = *(const ulonglong2*)(wA + (cg + 8 * cc) * WST + k);
                #pragma unroll
                for (int j = 0; j < 4; j++) {
                    FFMA2(accA[j][cc], h[j].x, w.x);
                    FFMA2(accA[j][cc], h[j].y, w.y);
                }
            }
        }
        if (CB) {
            #pragma unroll
            for (int cc = 0; cc < 2; cc++) {
                ulonglong2 w = *(const ulonglong2*)(wB + (cg + 8 * cc) * WST + k);
                #pragma unroll
                for (int j = 0; j < 4; j++) {
                    FFMA2(accB[j][cc], h[j].x, w.x);
                    FFMA2(accB[j][cc], h[j].y, w.y);
                }
            }
        }
    }
}

__global__ void __launch_bounds__(NTHR, 1) rnn_persistent(
    const int*   __restrict__ inputs, const float* __restrict__ emb,
    const float* __restrict__ b0,     const float* __restrict__ b1,
    const float* __restrict__ Wo,     const float* __restrict__ bo,
    float* __restrict__ out)
{
    const int tid = threadIdx.x;
    const int kq  = tid >> 7;
    const int t   = tid & 127;
    const int cg  = t & 7;             // cols cg, cg+8
    const int o   = t >> 3;            // rows o + 16j
    const int cb  = blockIdx.x * CPB;
    const unsigned int nc = gridDim.x;
    const int nh0 = UN / CK;           // 16

    for (int p = 0; p <= SEQT; ++p) {
        const bool dA = (p < SEQT);
        const bool dB = (p >= 1);
        const float* h0prev = g_h0[(p + 1) & 1];
        const float* h1prev = g_h1[p & 1];
        ull accA[4][2] = {}, accB[4][2] = {};

        const int nch = (dA ? 1 : 0) + nh0 + (dB ? nh0 : 0);
        auto decode = [&](int ci, int& ty, int& kc) {
            int x = ci;
            if (dA) { if (x == 0) { ty = 0; kc = 0; return; } x--; }
            if (x < nh0) { ty = 1; kc = x * CK; return; }
            ty = 2; kc = (x - nh0) * CK;
        };

        int ty, kc;
        decode(0, ty, kc);
        stage_chunk(ty, kc, p, 0, dA, dB, inputs, emb, h0prev, h1prev, cb, tid);
        CP_COMMIT();

        for (int g = 0; g < nch; ++g) {
            if (g + 1 < nch) {
                decode(g + 1, ty, kc);
                stage_chunk(ty, kc, p, (g + 1) % NBUF, dA, dB, inputs, emb,
                            h0prev, h1prev, cb, tid);
                CP_COMMIT();
                CP_WAIT1();
            } else {
                CP_WAIT0();
            }
            __syncthreads();
            int ty0, kc0; decode(g, ty0, kc0);
            const int b = g % NBUF;
            if (ty0 == 0)      gemm32<true,  false>(b, kq, o, cg, accA, accB);
            else if (ty0 == 1) {
                if (dA && dB)  gemm32<true,  true >(b, kq, o, cg, accA, accB);
                else if (dA)   gemm32<true,  false>(b, kq, o, cg, accA, accB);
                else           gemm32<false, true >(b, kq, o, cg, accA, accB);
            } else             gemm32<false, true >(b, kq, o, cg, accA, accB);
        }

        // ---- K-split reduction (4 partials) + activation + writeback ----
        __syncthreads();
        float* red = smem;                  // 512*16 floats = 32KB (h buf 0)
        float v[16];
        #pragma unroll
        for (int j = 0; j < 4; j++)
            #pragma unroll
            for (int cc = 0; cc < 2; cc++) {
                ull a = accA[j][cc], bq = accB[j][cc];
                v[j * 2 + cc]     = __uint_as_float((unsigned)(a & 0xffffffffull)) +
                                    __uint_as_float((unsigned)(a >> 32));
                v[8 + j * 2 + cc] = __uint_as_float((unsigned)(bq & 0xffffffffull)) +
                                    __uint_as_float((unsigned)(bq >> 32));
            }
        #pragma unroll
        for (int q = 0; q < 4; q++)
            *(float4*)(red + tid * 16 + q * 4) =
                make_float4(v[q * 4], v[q * 4 + 1], v[q * 4 + 2], v[q * 4 + 3]);
        __syncthreads();

        if (kq == 0) {
            #pragma unroll
            for (int idx = 0; idx < 16; idx++) {
                float s = red[t * 16 + idx] + red[(t + 128) * 16 + idx] +
                          red[(t + 256) * 16 + idx] + red[(t + 384) * 16 + idx];
                int loc = (idx < 8) ? idx : idx - 8;
                int j = loc >> 1, cc = loc & 1;
                int r = o + 16 * j;
                int gc = cb + cg + 8 * cc;
                if (idx < 8) {
                    if (dA) g_h0[p & 1][(size_t)r * UN + gc] = tanhf(s + b0[gc]);
                } else {
                    if (dB) g_h1[(p + 1) & 1][(size_t)r * UN + gc] = tanhf(s + b1[gc]);
                }
            }
        }
        gbar((unsigned)(p + 1) * nc);
    }

    // ---- final: out[b] = sigmoid(h1_{T-1} . Wo + bo) ----
    if (blockIdx.x == 0) {
        const float* h1f = g_h1[(SEQT - 1) & 1];
        const int warp = tid >> 5, lane = tid & 31;
        const float bof = bo[0];
        for (int r = warp; r < BATCH; r += NTHR / 32) {
            float s = 0.0f;
            for (int k = lane; k < UN; k += 32)
                s += h1f[(size_t)r * UN + k] * Wo[k];
            #pragma unroll
            for (int off = 16; off > 0; off >>= 1)
                s += __shfl_xor_sync(0xffffffffu, s, off);
            if (lane == 0)
                out[r] = 1.0f / (1.0f + expf(-(s + bof)));
        }
    }
}

extern "C" void kernel_launch(void* const* d_in, const int* in_sizes, int n_in,
                              void* d_out, int out_size)
{
    const int*   inputs = (const int*)  d_in[0];
    const float* emb    = (const float*)d_in[1];
    const float* Wx0    = (const float*)d_in[2];
    const float* Wh0    = (const float*)d_in[3];
    const float* b0     = (const float*)d_in[4];
    const float* Wx1    = (const float*)d_in[5];
    const float* Wh1    = (const float*)d_in[6];
    const float* b1     = (const float*)d_in[7];
    const float* Wo     = (const float*)d_in[8];
    const float* bo     = (const float*)d_in[9];
    float* out = (float*)d_out;

    float* wh0t; cudaGetSymbolAddress((void**)&wh0t, g_Wh0T);
    float* wx1t; cudaGetSymbolAddress((void**)&wx1t, g_Wx1T);
    float* wh1t; cudaGetSymbolAddress((void**)&wh1t, g_Wh1T);
    float* wx0t; cudaGetSymbolAddress((void**)&wx0t, g_Wx0T);

    dim3 tb(32, 8);
    transpose_pad<<<dim3(UN / 32, UN / 32), tb>>>(Wh0, wh0t, UN, UN, UN);
    transpose_pad<<<dim3(UN / 32, UN / 32), tb>>>(Wx1, wx1t, UN, UN, UN);
    transpose_pad<<<dim3(UN / 32, UN / 32), tb>>>(Wh1, wh1t, UN, UN, UN);
    transpose_pad<<<dim3(UN / 32, KPAD / 32), tb>>>(Wx0, wx0t, EMBD, UN, KPAD);

    const int smem_bytes = (NBUF * HSZ + NBUF * 2 * WSZ) * (int)sizeof(float); // 152064
    cudaFuncSetAttribute(rnn_persistent, cudaFuncAttributeMaxDynamicSharedMemorySize, smem_bytes);

    rnn_init_kernel<<<256, 256>>>();
    rnn_persistent<<<NCTA, NTHR, smem_bytes>>>(inputs, emb, b0, b1, Wo, bo, out);
}

// round 6
// speedup vs baseline: 2.2089x; 2.2089x over previous
#include <cuda_runtime.h>
#include <cuda_bf16.h>
#include <cstdint>

#define BATCH 64
#define SEQT  80
#define EMBD  100
#define KX    128
#define UN    2048
#define NCTA  128
#define NTHR  128
#define STGB  24576   // Ahi 8K | Alo 8K | Bhi 4K | Blo 4K
#define NBUF  3

__device__ __nv_bfloat16 g_h0hi[2][BATCH*UN], g_h0lo[2][BATCH*UN];
__device__ __nv_bfloat16 g_h1hi[2][BATCH*UN], g_h1lo[2][BATCH*UN];
__device__ __nv_bfloat16 g_Xhi[SEQT*BATCH*KX], g_Xlo[SEQT*BATCH*KX];
__device__ __nv_bfloat16 g_Wh0hi[UN*UN], g_Wh0lo[UN*UN];   // [n][k]
__device__ __nv_bfloat16 g_Wx1hi[UN*UN], g_Wx1lo[UN*UN];
__device__ __nv_bfloat16 g_Wh1hi[UN*UN], g_Wh1lo[UN*UN];
__device__ __nv_bfloat16 g_Wx0hi[UN*KX], g_Wx0lo[UN*KX];
__device__ unsigned g_gbar;

extern __shared__ char smem[];

__device__ __forceinline__ uint32_t smem_u32(const void* p) {
    uint32_t a;
    asm("{ .reg .u64 t; cvta.to.shared.u64 t, %1; cvt.u32.u64 %0, t; }" : "=r"(a) : "l"(p));
    return a;
}
__device__ __forceinline__ void cpcg(uint32_t d, const void* s) {
    asm volatile("cp.async.cg.shared.global [%0], [%1], 16;" :: "r"(d), "l"(s));
}
#define CP_COMMIT() asm volatile("cp.async.commit_group;" ::: "memory")
#define CP_WAIT1()  asm volatile("cp.async.wait_group 1;" ::: "memory")
#define CP_WAIT0()  asm volatile("cp.async.wait_group 0;" ::: "memory")

__device__ __forceinline__ void mma16816(float c[4], const uint32_t a[4], const uint32_t b[2]) {
    asm volatile("mma.sync.aligned.m16n8k16.row.col.f32.bf16.bf16.f32 "
        "{%0,%1,%2,%3}, {%4,%5,%6,%7}, {%8,%9}, {%0,%1,%2,%3};"
        : "+f"(c[0]), "+f"(c[1]), "+f"(c[2]), "+f"(c[3])
        : "r"(a[0]), "r"(a[1]), "r"(a[2]), "r"(a[3]), "r"(b[0]), "r"(b[1]));
}

// ---- prep kernels ----
__global__ void wsplit(const float* __restrict__ src, __nv_bfloat16* __restrict__ hi,
                       __nv_bfloat16* __restrict__ lo, int K, int N, int Kpad) {
    __shared__ float tile[32][33];
    int kb = blockIdx.y * 32, nb = blockIdx.x * 32;
    int tx = threadIdx.x, ty = threadIdx.y;
    #pragma unroll
    for (int j = 0; j < 32; j += 8) {
        int k = kb + ty + j;
        tile[ty + j][tx] = (k < K) ? src[(size_t)k * N + nb + tx] : 0.0f;
    }
    __syncthreads();
    #pragma unroll
    for (int j = 0; j < 32; j += 8) {
        int n = nb + ty + j, k = kb + tx;
        if (k < Kpad) {
            float v = tile[tx][ty + j];
            __nv_bfloat16 h = __float2bfloat16(v);
            hi[(size_t)n * Kpad + k] = h;
            lo[(size_t)n * Kpad + k] = __float2bfloat16(v - __bfloat162float(h));
        }
    }
}
__global__ void xprep(const int* __restrict__ inputs, const float* __restrict__ emb) {
    int idx = blockIdx.x * blockDim.x + threadIdx.x;
    if (idx >= SEQT * BATCH * KX) return;
    int k = idx & 127, b = (idx >> 7) & 63, t = idx >> 13;
    float v = (k < EMBD) ? emb[(size_t)inputs[b * SEQT + t] * EMBD + k] : 0.0f;
    __nv_bfloat16 h = __float2bfloat16(v);
    g_Xhi[idx] = h;
    g_Xlo[idx] = __float2bfloat16(v - __bfloat162float(h));
}
__global__ void hzero() {
    int idx = blockIdx.x * blockDim.x + threadIdx.x;
    __nv_bfloat16 z = __float2bfloat16(0.0f);
    for (int i = idx; i < BATCH * UN; i += gridDim.x * blockDim.x) {
        g_h0hi[1][i] = z; g_h0lo[1][i] = z;
        g_h1hi[1][i] = z; g_h1lo[1][i] = z;
    }
    if (idx == 0) g_gbar = 0u;
}

__device__ __forceinline__ void gbar(unsigned target) {
    __syncthreads();
    if (threadIdx.x == 0) {
        __threadfence();
        atomicAdd(&g_gbar, 1u);
        unsigned v;
        do {
            asm volatile("ld.acquire.gpu.u32 %0, [%1];" : "=r"(v) : "l"(&g_gbar) : "memory");
        } while (v < target);
    }
    __syncthreads();
}

// Stage one k64 chunk: A hi/lo 64x64 bf16, B hi/lo 32x64 bf16, SW-swizzled 128B rows.
__device__ __forceinline__ void stage_g(int g, bool isA, int p, int par0, int par1,
                                        int cb, uint32_t sb, int tid) {
    const __nv_bfloat16 *ahi, *alo, *bhi, *blo;
    size_t astr = UN, bstr = UN;
    if (isA) {
        if (g < 2) {
            int kc = g * 64;
            ahi = g_Xhi + (size_t)p * BATCH * KX + kc;
            alo = g_Xlo + (size_t)p * BATCH * KX + kc;  astr = KX;
            bhi = g_Wx0hi + (size_t)cb * KX + kc;
            blo = g_Wx0lo + (size_t)cb * KX + kc;       bstr = KX;
        } else {
            int kc = (g - 2) * 64;
            ahi = g_h0hi[par0] + kc;  alo = g_h0lo[par0] + kc;
            bhi = g_Wh0hi + (size_t)cb * UN + kc;
            blo = g_Wh0lo + (size_t)cb * UN + kc;
        }
    } else {
        if (g < 32) {
            int kc = g * 64;
            ahi = g_h0hi[par0] + kc;  alo = g_h0lo[par0] + kc;
            bhi = g_Wx1hi + (size_t)cb * UN + kc;
            blo = g_Wx1lo + (size_t)cb * UN + kc;
        } else {
            int kc = (g - 32) * 64;
            ahi = g_h1hi[par1] + kc;  alo = g_h1lo[par1] + kc;
            bhi = g_Wh1hi + (size_t)cb * UN + kc;
            blo = g_Wh1lo + (size_t)cb * UN + kc;
        }
    }
    #pragma unroll
    for (int j = 0; j < 4; j++) {          // A: 64 rows x 8 units, hi+lo
        int i = tid + NTHR * j;
        int r = i >> 3, q = i & 7;
        uint32_t off = (uint32_t)(r * 128 + ((q ^ (r & 7)) << 4));
        cpcg(sb + off,        ahi + (size_t)r * astr + q * 8);
        cpcg(sb + 8192 + off, alo + (size_t)r * astr + q * 8);
    }
    #pragma unroll
    for (int j = 0; j < 2; j++) {          // B: 32 rows x 8 units, hi+lo
        int i = tid + NTHR * j;
        int r = i >> 3, q = i & 7;
        uint32_t off = (uint32_t)(r * 128 + ((q ^ (r & 7)) << 4));
        cpcg(sb + 16384 + off, bhi + (size_t)r * bstr + q * 8);
        cpcg(sb + 20480 + off, blo + (size_t)r * bstr + q * 8);
    }
}

// Compute one k64 chunk. 3-term split MMA into fp32 acc.
__device__ __forceinline__ void gemm_chunk(const char* sb, const int ra[2], const int rb[2],
                                           int gr, float acc[2][2][4]) {
    const char* sAh = sb;
    const char* sAl = sb + 8192;
    const char* sBh = sb + 16384;
    const char* sBl = sb + 20480;
    #pragma unroll
    for (int kk = 0; kk < 4; kk++) {
        const int u0 = ((2 * kk)     ^ gr) << 4;
        const int u1 = ((2 * kk + 1) ^ gr) << 4;
        uint32_t ah[2][4], al[2][4], bh[2][2], bl[2][2];
        #pragma unroll
        for (int mt = 0; mt < 2; mt++) {
            ah[mt][0] = *(const uint32_t*)(sAh + ra[mt] + u0);
            ah[mt][1] = *(const uint32_t*)(sAh + ra[mt] + 1024 + u0);
            ah[mt][2] = *(const uint32_t*)(sAh + ra[mt] + u1);
            ah[mt][3] = *(const uint32_t*)(sAh + ra[mt] + 1024 + u1);
            al[mt][0] = *(const uint32_t*)(sAl + ra[mt] + u0);
            al[mt][1] = *(const uint32_t*)(sAl + ra[mt] + 1024 + u0);
            al[mt][2] = *(const uint32_t*)(sAl + ra[mt] + u1);
            al[mt][3] = *(const uint32_t*)(sAl + ra[mt] + 1024 + u1);
        }
        #pragma unroll
        for (int nt = 0; nt < 2; nt++) {
            bh[nt][0] = *(const uint32_t*)(sBh + rb[nt] + u0);
            bh[nt][1] = *(const uint32_t*)(sBh + rb[nt] + u1);
            bl[nt][0] = *(const uint32_t*)(sBl + rb[nt] + u0);
            bl[nt][1] = *(const uint32_t*)(sBl + rb[nt] + u1);
        }
        #pragma unroll
        for (int mt = 0; mt < 2; mt++)
            #pragma unroll
            for (int nt = 0; nt < 2; nt++) {
                mma16816(acc[mt][nt], ah[mt], bh[nt]);
                mma16816(acc[mt][nt], ah[mt], bl[nt]);
                mma16816(acc[mt][nt], al[mt], bh[nt]);
            }
    }
}

__global__ void __launch_bounds__(NTHR, 1) rnn_mma(
    const float* __restrict__ b0, const float* __restrict__ b1,
    const float* __restrict__ Wo, const float* __restrict__ bo,
    float* __restrict__ out)
{
    const int tid = threadIdx.x;
    const int wid = tid >> 5, lane = tid & 31;
    const int wm = wid >> 1, wn = wid & 1;
    const int gr = lane >> 2, gc = lane & 3;
    const bool isA = (blockIdx.x < 64);
    const int cb = (blockIdx.x & 63) * 32;
    const int nch = isA ? 34 : 64;
    const float* bias = isA ? b0 : b1;
    uint32_t su = smem_u32(smem);

    int ra[2], rb[2];
    #pragma unroll
    for (int mt = 0; mt < 2; mt++) ra[mt] = (wm * 32 + mt * 16 + gr) * 128 + gc * 4;
    #pragma unroll
    for (int nt = 0; nt < 2; nt++) rb[nt] = (wn * 16 + nt * 8 + gr) * 128 + gc * 4;

    float bb[2][2];
    #pragma unroll
    for (int nt = 0; nt < 2; nt++) {
        int c = cb + wn * 16 + nt * 8 + 2 * gc;
        bb[nt][0] = bias[c]; bb[nt][1] = bias[c + 1];
    }

    for (int p = 0; p <= SEQT; p++) {
        const bool active = isA ? (p < SEQT) : (p >= 1);
        if (active) {
            const int par0 = (p + 1) & 1, par1 = p & 1;
            float acc[2][2][4] = {};

            stage_g(0, isA, p, par0, par1, cb, su, tid);
            CP_COMMIT();
            for (int g = 0; g < nch; g++) {
                if (g + 1 < nch) {
                    stage_g(g + 1, isA, p, par0, par1, cb,
                            su + (uint32_t)((g + 1) % NBUF) * STGB, tid);
                    CP_COMMIT();
                    CP_WAIT1();
                } else {
                    CP_WAIT0();
                }
                __syncthreads();
                gemm_chunk(smem + (g % NBUF) * STGB, ra, rb, gr, acc);
            }

            // ---- epilogue: bias + tanh + hi/lo split, direct from regs ----
            __nv_bfloat16* dhi = isA ? g_h0hi[p & 1] : g_h1hi[(p + 1) & 1];
            __nv_bfloat16* dlo = isA ? g_h0lo[p & 1] : g_h1lo[(p + 1) & 1];
            #pragma unroll
            for (int mt = 0; mt < 2; mt++) {
                #pragma unroll
                for (int nt = 0; nt < 2; nt++) {
                    int r0 = wm * 32 + mt * 16 + gr;
                    int c0 = cb + wn * 16 + nt * 8 + 2 * gc;
                    #pragma unroll
                    for (int hrow = 0; hrow < 2; hrow++) {
                        int r = r0 + hrow * 8;
                        float s0 = tanhf(acc[mt][nt][hrow * 2]     + bb[nt][0]);
                        float s1 = tanhf(acc[mt][nt][hrow * 2 + 1] + bb[nt][1]);
                        __nv_bfloat16 h0 = __float2bfloat16(s0), h1 = __float2bfloat16(s1);
                        __nv_bfloat16 l0 = __float2bfloat16(s0 - __bfloat162float(h0));
                        __nv_bfloat16 l1 = __float2bfloat16(s1 - __bfloat162float(h1));
                        size_t off = (size_t)r * UN + c0;
                        *(__nv_bfloat162*)(dhi + off) = __nv_bfloat162(h0, h1);
                        *(__nv_bfloat162*)(dlo + off) = __nv_bfloat162(l0, l1);
                    }
                }
            }
        }
        gbar((unsigned)(p + 1) * NCTA);
    }

    // ---- out[b] = sigmoid(h1_final . Wo + bo); h1_final in parity 1 ----
    if (blockIdx.x == 0) {
        const __nv_bfloat16* hh = g_h1hi[1];
        const __nv_bfloat16* hl = g_h1lo[1];
        const float bof = bo[0];
        for (int r = wid; r < BATCH; r += 4) {
            float s = 0.0f;
            for (int k = lane; k < UN; k += 32)
                s += (__bfloat162float(hh[(size_t)r * UN + k]) +
                      __bfloat162float(hl[(size_t)r * UN + k])) * Wo[k];
            #pragma unroll
            for (int o = 16; o > 0; o >>= 1)
                s += __shfl_xor_sync(0xffffffffu, s, o);
            if (lane == 0) out[r] = 1.0f / (1.0f + expf(-(s + bof)));
        }
    }
}

extern "C" void kernel_launch(void* const* d_in, const int* in_sizes, int n_in,
                              void* d_out, int out_size)
{
    const int*   inputs = (const int*)  d_in[0];
    const float* emb    = (const float*)d_in[1];
    const float* Wx0    = (const float*)d_in[2];
    const float* Wh0    = (const float*)d_in[3];
    const float* b0     = (const float*)d_in[4];
    const float* Wx1    = (const float*)d_in[5];
    const float* Wh1    = (const float*)d_in[6];
    const float* b1     = (const float*)d_in[7];
    const float* Wo     = (const float*)d_in[8];
    const float* bo     = (const float*)d_in[9];
    float* out = (float*)d_out;

    __nv_bfloat16 *wh0h, *wh0l, *wx1h, *wx1l, *wh1h, *wh1l, *wx0h, *wx0l;
    cudaGetSymbolAddress((void**)&wh0h, g_Wh0hi); cudaGetSymbolAddress((void**)&wh0l, g_Wh0lo);
    cudaGetSymbolAddress((void**)&wx1h, g_Wx1hi); cudaGetSymbolAddress((void**)&wx1l, g_Wx1lo);
    cudaGetSymbolAddress((void**)&wh1h, g_Wh1hi); cudaGetSymbolAddress((void**)&wh1l, g_Wh1lo);
    cudaGetSymbolAddress((void**)&wx0h, g_Wx0hi); cudaGetSymbolAddress((void**)&wx0l, g_Wx0lo);

    dim3 tb(32, 8);
    wsplit<<<dim3(UN/32, UN/32), tb>>>(Wh0, wh0h, wh0l, UN, UN, UN);
    wsplit<<<dim3(UN/32, UN/32), tb>>>(Wx1, wx1h, wx1l, UN, UN, UN);
    wsplit<<<dim3(UN/32, UN/32), tb>>>(Wh1, wh1h, wh1l, UN, UN, UN);
    wsplit<<<dim3(UN/32, KX/32),  tb>>>(Wx0, wx0h, wx0l, EMBD, UN, KX);
    xprep<<<(SEQT*BATCH*KX + 255)/256, 256>>>(inputs, emb);
    hzero<<<256, 256>>>();

    const int smem_bytes = NBUF * STGB;   // 73728
    cudaFuncSetAttribute(rnn_mma, cudaFuncAttributeMaxDynamicSharedMemorySize, smem_bytes);
    rnn_mma<<<NCTA, NTHR, smem_bytes>>>(b0, b1, Wo, bo, out);
}

// round 7
// speedup vs baseline: 2.3180x; 1.0494x over previous
#include <cuda_runtime.h>
#include <cuda_bf16.h>
#include <cstdint>

#define BATCH 64
#define SEQT  80
#define EMBD  100
#define KX    128
#define UN    2048
#define NCTA  128
#define NTHR  256
#define STGB  24576   // Ahi 8K | Alo 8K | Bhi 4K | Blo 4K
#define NBUF  3

__device__ __nv_bfloat16 g_h0hi[2][BATCH*UN], g_h0lo[2][BATCH*UN];
__device__ __nv_bfloat16 g_h1hi[2][BATCH*UN], g_h1lo[2][BATCH*UN];
__device__ __nv_bfloat16 g_Xhi[SEQT*BATCH*KX], g_Xlo[SEQT*BATCH*KX];
__device__ __nv_bfloat16 g_Wh0hi[UN*UN], g_Wh0lo[UN*UN];   // [n][k]
__device__ __nv_bfloat16 g_Wx1hi[UN*UN], g_Wx1lo[UN*UN];
__device__ __nv_bfloat16 g_Wh1hi[UN*UN], g_Wh1lo[UN*UN];
__device__ __nv_bfloat16 g_Wx0hi[UN*KX], g_Wx0lo[UN*KX];
__device__ unsigned g_gbar;

extern __shared__ char smem[];

__device__ __forceinline__ uint32_t smem_u32(const void* p) {
    uint32_t a;
    asm("{ .reg .u64 t; cvta.to.shared.u64 t, %1; cvt.u32.u64 %0, t; }" : "=r"(a) : "l"(p));
    return a;
}
__device__ __forceinline__ void cpcg(uint32_t d, const void* s) {
    asm volatile("cp.async.cg.shared.global [%0], [%1], 16;" :: "r"(d), "l"(s));
}
#define CP_COMMIT() asm volatile("cp.async.commit_group;" ::: "memory")
#define CP_WAIT1()  asm volatile("cp.async.wait_group 1;" ::: "memory")
#define CP_WAIT0()  asm volatile("cp.async.wait_group 0;" ::: "memory")

__device__ __forceinline__ void mma16816(float c[4], const uint32_t a[4], const uint32_t b[2]) {
    asm volatile("mma.sync.aligned.m16n8k16.row.col.f32.bf16.bf16.f32 "
        "{%0,%1,%2,%3}, {%4,%5,%6,%7}, {%8,%9}, {%0,%1,%2,%3};"
        : "+f"(c[0]), "+f"(c[1]), "+f"(c[2]), "+f"(c[3])
        : "r"(a[0]), "r"(a[1]), "r"(a[2]), "r"(a[3]), "r"(b[0]), "r"(b[1]));
}
__device__ __forceinline__ void ldm4(uint32_t r[4], uint32_t addr) {
    asm volatile("ldmatrix.sync.aligned.m8n8.x4.shared.b16 {%0,%1,%2,%3}, [%4];"
        : "=r"(r[0]), "=r"(r[1]), "=r"(r[2]), "=r"(r[3]) : "r"(addr));
}

// ---- prep kernels ----
__global__ void wsplit(const float* __restrict__ src, __nv_bfloat16* __restrict__ hi,
                       __nv_bfloat16* __restrict__ lo, int K, int N, int Kpad) {
    __shared__ float tile[32][33];
    int kb = blockIdx.y * 32, nb = blockIdx.x * 32;
    int tx = threadIdx.x, ty = threadIdx.y;
    #pragma unroll
    for (int j = 0; j < 32; j += 8) {
        int k = kb + ty + j;
        tile[ty + j][tx] = (k < K) ? src[(size_t)k * N + nb + tx] : 0.0f;
    }
    __syncthreads();
    #pragma unroll
    for (int j = 0; j < 32; j += 8) {
        int n = nb + ty + j, k = kb + tx;
        if (k < Kpad) {
            float v = tile[tx][ty + j];
            __nv_bfloat16 h = __float2bfloat16(v);
            hi[(size_t)n * Kpad + k] = h;
            lo[(size_t)n * Kpad + k] = __float2bfloat16(v - __bfloat162float(h));
        }
    }
}
__global__ void xprep(const int* __restrict__ inputs, const float* __restrict__ emb) {
    int idx = blockIdx.x * blockDim.x + threadIdx.x;
    if (idx >= SEQT * BATCH * KX) return;
    int k = idx & 127, b = (idx >> 7) & 63, t = idx >> 13;
    float v = (k < EMBD) ? emb[(size_t)inputs[b * SEQT + t] * EMBD + k] : 0.0f;
    __nv_bfloat16 h = __float2bfloat16(v);
    g_Xhi[idx] = h;
    g_Xlo[idx] = __float2bfloat16(v - __bfloat162float(h));
}
__global__ void hzero() {
    int idx = blockIdx.x * blockDim.x + threadIdx.x;
    __nv_bfloat16 z = __float2bfloat16(0.0f);
    for (int i = idx; i < BATCH * UN; i += gridDim.x * blockDim.x) {
        g_h0hi[1][i] = z; g_h0lo[1][i] = z;
        g_h1hi[1][i] = z; g_h1lo[1][i] = z;
    }
    if (idx == 0) g_gbar = 0u;
}

__device__ __forceinline__ void gbar(unsigned target) {
    __syncthreads();
    if (threadIdx.x == 0) {
        __threadfence();
        atomicAdd(&g_gbar, 1u);
        unsigned v;
        do {
            asm volatile("ld.acquire.gpu.u32 %0, [%1];" : "=r"(v) : "l"(&g_gbar) : "memory");
        } while (v < target);
    }
    __syncthreads();
}

// Stage one k64 chunk: A hi/lo 64x64 bf16, B hi/lo 32x64 bf16, 16B-XOR swizzle.
__device__ __forceinline__ void stage_g(int g, bool isA, int p, int par0, int par1,
                                        int cb, uint32_t sb, int tid) {
    const __nv_bfloat16 *ahi, *alo, *bhi, *blo;
    size_t astr = UN, bstr = UN;
    if (isA) {
        if (g < 2) {
            int kc = g * 64;
            ahi = g_Xhi + (size_t)p * BATCH * KX + kc;
            alo = g_Xlo + (size_t)p * BATCH * KX + kc;  astr = KX;
            bhi = g_Wx0hi + (size_t)cb * KX + kc;
            blo = g_Wx0lo + (size_t)cb * KX + kc;       bstr = KX;
        } else {
            int kc = (g - 2) * 64;
            ahi = g_h0hi[par0] + kc;  alo = g_h0lo[par0] + kc;
            bhi = g_Wh0hi + (size_t)cb * UN + kc;
            blo = g_Wh0lo + (size_t)cb * UN + kc;
        }
    } else {
        if (g < 32) {
            int kc = g * 64;
            ahi = g_h0hi[par0] + kc;  alo = g_h0lo[par0] + kc;
            bhi = g_Wx1hi + (size_t)cb * UN + kc;
            blo = g_Wx1lo + (size_t)cb * UN + kc;
        } else {
            int kc = (g - 32) * 64;
            ahi = g_h1hi[par1] + kc;  alo = g_h1lo[par1] + kc;
            bhi = g_Wh1hi + (size_t)cb * UN + kc;
            blo = g_Wh1lo + (size_t)cb * UN + kc;
        }
    }
    #pragma unroll
    for (int j = 0; j < 2; j++) {            // A: 64 rows x 8 units, hi+lo
        int i = tid + NTHR * j;
        int r = i >> 3, q = i & 7;
        uint32_t off = (uint32_t)(r * 128 + ((q ^ (r & 7)) << 4));
        cpcg(sb + off,        ahi + (size_t)r * astr + q * 8);
        cpcg(sb + 8192 + off, alo + (size_t)r * astr + q * 8);
    }
    {                                        // B: 32 rows x 8 units, hi+lo
        int r = tid >> 3, q = tid & 7;
        uint32_t off = (uint32_t)(r * 128 + ((q ^ (r & 7)) << 4));
        cpcg(sb + 16384 + off, bhi + (size_t)r * bstr + q * 8);
        cpcg(sb + 20480 + off, blo + (size_t)r * bstr + q * 8);
    }
}

// Compute this warp-group's k32 half of a k64 chunk via ldmatrix + 3-term MMA.
__device__ __forceinline__ void gemm_chunk(uint32_t sb, int wk,
    const int offA[2], const int r7A[2], int offB, int r7B,
    int uAl, int uBl, float acc[2][2][4])
{
    #pragma unroll
    for (int kk = 0; kk < 2; kk++) {
        const int q0 = (wk * 2 + kk) * 2;
        uint32_t ah[2][4], al[2][4], bh[4], bl[4];
        #pragma unroll
        for (int mt = 0; mt < 2; mt++) {
            uint32_t ao = sb + offA[mt] + (uint32_t)(((q0 + uAl) ^ r7A[mt]) << 4);
            ldm4(ah[mt], ao);
            ldm4(al[mt], ao + 8192);
        }
        uint32_t bo = sb + 16384 + offB + (uint32_t)(((q0 + uBl) ^ r7B) << 4);
        ldm4(bh, bo);
        ldm4(bl, bo + 4096);
        #pragma unroll
        for (int mt = 0; mt < 2; mt++)
            #pragma unroll
            for (int nt = 0; nt < 2; nt++) {
                mma16816(acc[mt][nt], ah[mt], bh + nt * 2);
                mma16816(acc[mt][nt], ah[mt], bl + nt * 2);
                mma16816(acc[mt][nt], al[mt], bh + nt * 2);
            }
    }
}

__global__ void __launch_bounds__(NTHR, 1) rnn_mma(
    const float* __restrict__ b0, const float* __restrict__ b1,
    const float* __restrict__ Wo, const float* __restrict__ bo,
    float* __restrict__ out)
{
    const int tid = threadIdx.x;
    const int wid = tid >> 5, lane = tid & 31;
    const int wk = wid >> 2;              // k-half 0/1
    const int wsub = wid & 3;
    const int wm = wsub >> 1, wn = wsub & 1;
    const int gr = lane >> 2, gc = lane & 3;
    const bool isA = (blockIdx.x < 64);
    const int cb = (blockIdx.x & 63) * 32;
    const int nch = isA ? 34 : 64;
    const float* bias = isA ? b0 : b1;
    uint32_t su = smem_u32(smem);

    // ldmatrix per-lane row precompute
    int offA[2], r7A[2];
    #pragma unroll
    for (int mt = 0; mt < 2; mt++) {
        int r = wm * 32 + mt * 16 + (lane & 15);
        offA[mt] = r * 128;  r7A[mt] = r & 7;
    }
    const int nB = wn * 16 + (lane & 7) + ((lane >> 4) << 3);
    const int offB = nB * 128, r7B = nB & 7;
    const int uAl = lane >> 4;            // 0/1
    const int uBl = (lane >> 3) & 1;      // 0/1

    float bb[2][2];
    #pragma unroll
    for (int nt = 0; nt < 2; nt++) {
        int c = cb + wn * 16 + nt * 8 + 2 * gc;
        bb[nt][0] = bias[c]; bb[nt][1] = bias[c + 1];
    }

    for (int p = 0; p <= SEQT; p++) {
        const bool active = isA ? (p < SEQT) : (p >= 1);
        if (active) {
            const int par0 = (p + 1) & 1, par1 = p & 1;
            float acc[2][2][4] = {};

            stage_g(0, isA, p, par0, par1, cb, su, tid);
            CP_COMMIT();
            for (int g = 0; g < nch; g++) {
                if (g + 1 < nch) {
                    stage_g(g + 1, isA, p, par0, par1, cb,
                            su + (uint32_t)((g + 1) % NBUF) * STGB, tid);
                    CP_COMMIT();
                    CP_WAIT1();
                } else {
                    CP_WAIT0();
                }
                __syncthreads();
                gemm_chunk(su + (uint32_t)(g % NBUF) * STGB, wk,
                           offA, r7A, offB, r7B, uAl, uBl, acc);
            }

            // ---- cross-k-half reduction through smem ----
            __syncthreads();                      // all compute done
            float* red = (float*)smem;            // 8KB in stage buf 0
            float* af = &acc[0][0][0];
            if (wk == 1) {
                #pragma unroll
                for (int i = 0; i < 16; i++) red[i * 128 + (tid & 127)] = af[i];
            }
            __syncthreads();
            if (wk == 0) {
                #pragma unroll
                for (int i = 0; i < 16; i++) af[i] += red[i * 128 + tid];

                // ---- epilogue: bias + tanh + hi/lo split ----
                __nv_bfloat16* dhi = isA ? g_h0hi[p & 1] : g_h1hi[(p + 1) & 1];
                __nv_bfloat16* dlo = isA ? g_h0lo[p & 1] : g_h1lo[(p + 1) & 1];
                #pragma unroll
                for (int mt = 0; mt < 2; mt++)
                    #pragma unroll
                    for (int nt = 0; nt < 2; nt++) {
                        int r0 = wm * 32 + mt * 16 + gr;
                        int c0 = cb + wn * 16 + nt * 8 + 2 * gc;
                        #pragma unroll
                        for (int hrow = 0; hrow < 2; hrow++) {
                            int r = r0 + hrow * 8;
                            float s0 = tanhf(acc[mt][nt][hrow * 2]     + bb[nt][0]);
                            float s1 = tanhf(acc[mt][nt][hrow * 2 + 1] + bb[nt][1]);
                            __nv_bfloat16 h0 = __float2bfloat16(s0), h1 = __float2bfloat16(s1);
                            __nv_bfloat16 l0 = __float2bfloat16(s0 - __bfloat162float(h0));
                            __nv_bfloat16 l1 = __float2bfloat16(s1 - __bfloat162float(h1));
                            size_t off = (size_t)r * UN + c0;
                            *(__nv_bfloat162*)(dhi + off) = __nv_bfloat162(h0, h1);
                            *(__nv_bfloat162*)(dlo + off) = __nv_bfloat162(l0, l1);
                        }
                    }
            }
        }
        gbar((unsigned)(p + 1) * NCTA);
    }

    // ---- out[b] = sigmoid(h1_final . Wo + bo); h1_final in parity 1 ----
    if (blockIdx.x == 0) {
        const __nv_bfloat16* hh = g_h1hi[1];
        const __nv_bfloat16* hl = g_h1lo[1];
        const float bof = bo[0];
        for (int r = wid; r < BATCH; r += 8) {
            float s = 0.0f;
            for (int k = lane; k < UN; k += 32)
                s += (__bfloat162float(hh[(size_t)r * UN + k]) +
                      __bfloat162float(hl[(size_t)r * UN + k])) * Wo[k];
            #pragma unroll
            for (int o = 16; o > 0; o >>= 1)
                s += __shfl_xor_sync(0xffffffffu, s, o);
            if (lane == 0) out[r] = 1.0f / (1.0f + expf(-(s + bof)));
        }
    }
}

extern "C" void kernel_launch(void* const* d_in, const int* in_sizes, int n_in,
                              void* d_out, int out_size)
{
    const int*   inputs = (const int*)  d_in[0];
    const float* emb    = (const float*)d_in[1];
    const float* Wx0    = (const float*)d_in[2];
    const float* Wh0    = (const float*)d_in[3];
    const float* b0     = (const float*)d_in[4];
    const float* Wx1    = (const float*)d_in[5];
    const float* Wh1    = (const float*)d_in[6];
    const float* b1     = (const float*)d_in[7];
    const float* Wo     = (const float*)d_in[8];
    const float* bo     = (const float*)d_in[9];
    float* out = (float*)d_out;

    __nv_bfloat16 *wh0h, *wh0l, *wx1h, *wx1l, *wh1h, *wh1l, *wx0h, *wx0l;
    cudaGetSymbolAddress((void**)&wh0h, g_Wh0hi); cudaGetSymbolAddress((void**)&wh0l, g_Wh0lo);
    cudaGetSymbolAddress((void**)&wx1h, g_Wx1hi); cudaGetSymbolAddress((void**)&wx1l, g_Wx1lo);
    cudaGetSymbolAddress((void**)&wh1h, g_Wh1hi); cudaGetSymbolAddress((void**)&wh1l, g_Wh1lo);
    cudaGetSymbolAddress((void**)&wx0h, g_Wx0hi); cudaGetSymbolAddress((void**)&wx0l, g_Wx0lo);

    dim3 tb(32, 8);
    wsplit<<<dim3(UN/32, UN/32), tb>>>(Wh0, wh0h, wh0l, UN, UN, UN);
    wsplit<<<dim3(UN/32, UN/32), tb>>>(Wx1, wx1h, wx1l, UN, UN, UN);
    wsplit<<<dim3(UN/32, UN/32), tb>>>(Wh1, wh1h, wh1l, UN, UN, UN);
    wsplit<<<dim3(UN/32, KX/32),  tb>>>(Wx0, wx0h, wx0l, EMBD, UN, KX);
    xprep<<<(SEQT*BATCH*KX + 255)/256, 256>>>(inputs, emb);
    hzero<<<256, 256>>>();

    const int smem_bytes = NBUF * STGB;   // 73728
    cudaFuncSetAttribute(rnn_mma, cudaFuncAttributeMaxDynamicSharedMemorySize, smem_bytes);
    rnn_mma<<<NCTA, NTHR, smem_bytes>>>(b0, b1, Wo, bo, out);
}